// round 4
// baseline (speedup 1.0000x reference)
#include <cuda_runtime.h>
#include <cstdint>

// Locally-connected 2D: out[oy,ox] = sum_{ky,kx} x[oy+ky, ox+kx] * W[oy,ox,ky,kx]
// x: [450,450] f32, W: [436,436,15,15] f32 (171 MB streamed once), out: [436,436].
// TMA-bulk (cp.async.bulk) double-buffered streaming of W through smem,
// bypassing the L1tex LDG path. Block = half an output row; x staged once.

#define IN_H 450
#define IN_W 450
#define KH 15
#define KW 15
#define OH 436
#define OW 436
#define KSIZE 225
#define TPX 32              // pixels per W tile (28800 B)
#define HALF0 224           // pixels in first half-row
#define XC 240              // padded x columns in smem
#define THREADS 256

// dynamic smem layout (bytes):
//  [0,     57600)  W ring: 2 slots x 32*225 floats
//  [57600, 72000)  Xsm: 15 x 240 floats
//  [72000, 73024)  Red: 256 floats
//  [73024, 73040)  mbar[2] (u64)
#define SMEM_W    0
#define SMEM_X    57600
#define SMEM_RED  72000
#define SMEM_MBAR 73024
#define SMEM_TOTAL 73056

__device__ __forceinline__ void mbar_init(uint32_t mbar, uint32_t count) {
    asm volatile("mbarrier.init.shared.b64 [%0], %1;" :: "r"(mbar), "r"(count) : "memory");
}
__device__ __forceinline__ void mbar_expect_tx(uint32_t mbar, uint32_t bytes) {
    asm volatile("mbarrier.arrive.expect_tx.shared.b64 _, [%0], %1;"
                 :: "r"(mbar), "r"(bytes) : "memory");
}
__device__ __forceinline__ void mbar_wait(uint32_t mbar, uint32_t parity) {
    asm volatile(
        "{\n\t"
        ".reg .pred P;\n\t"
        "WAIT_%=:\n\t"
        "mbarrier.try_wait.parity.acquire.cta.shared::cta.b64 P, [%0], %1, 0x989680;\n\t"
        "@!P bra WAIT_%=;\n\t"
        "}"
        :: "r"(mbar), "r"(parity) : "memory");
}
__device__ __forceinline__ void tma_bulk_g2s(uint32_t dst, const float* src,
                                             uint32_t bytes, uint32_t mbar) {
    asm volatile(
        "cp.async.bulk.shared::cluster.global.mbarrier::complete_tx::bytes [%0], [%1], %2, [%3];"
        :: "r"(dst), "l"(src), "r"(bytes), "r"(mbar) : "memory");
}

__global__ __launch_bounds__(THREADS)
void lc2d_kernel(const float* __restrict__ x,
                 const float* __restrict__ W,
                 float* __restrict__ out)
{
    extern __shared__ __align__(128) char smem[];
    float* Wbuf = (float*)(smem + SMEM_W);
    float* Xsm  = (float*)(smem + SMEM_X);
    float* Red  = (float*)(smem + SMEM_RED);
    const uint32_t smem_u32 = (uint32_t)__cvta_generic_to_shared(smem);
    const uint32_t wslot_u32 = smem_u32 + SMEM_W;
    const uint32_t mbar0 = smem_u32 + SMEM_MBAR;

    const int tid  = threadIdx.x;
    const int row  = blockIdx.y;
    const int half = blockIdx.x;
    const int px0  = half * HALF0;
    const int npx_blk = half ? (OW - HALF0) : HALF0;   // 212 or 224
    const int ntiles  = (npx_blk + TPX - 1) / TPX;     // 7
    const int xcols   = npx_blk + KW - 1;              // 238 or 226

    if (tid == 0) {
        mbar_init(mbar0, 1);
        mbar_init(mbar0 + 8, 1);
    }

    // Stage x span for this half-row once (reused by all 7 tiles).
    for (int i = tid; i < KH * xcols; i += THREADS) {
        const int r = i / xcols;
        const int c = i - r * xcols;
        Xsm[r * XC + c] = __ldg(x + (row + r) * IN_W + px0 + c);
    }
    __syncthreads();   // mbar init + Xsm visible to all

    const float* Wg = W + (size_t)(row * OW + px0) * KSIZE;

    // Prologue: fill both slots.
    if (tid == 0) {
        {
            const uint32_t bytes = (uint32_t)(min(TPX, npx_blk) * KSIZE * 4);
            mbar_expect_tx(mbar0, bytes);
            tma_bulk_g2s(wslot_u32, Wg, bytes, mbar0);
        }
        if (ntiles > 1) {
            const uint32_t bytes = (uint32_t)(min(TPX, npx_blk - TPX) * KSIZE * 4);
            mbar_expect_tx(mbar0 + 8, bytes);
            tma_bulk_g2s(wslot_u32 + TPX * KSIZE * 4, Wg + (size_t)TPX * KSIZE, bytes, mbar0 + 8);
        }
    }

    const int p    = tid & 31;     // pixel within tile
    const int part = tid >> 5;     // ky pair: rows {2*part, 2*part+1}

    for (int t = 0; t < ntiles; t++) {
        const int slot = t & 1;
        mbar_wait(mbar0 + 8 * slot, (t >> 1) & 1);

        const int pl = t * TPX + p;          // pixel local to block
        float sum = 0.0f;
        if (pl < npx_blk) {
            const float* wp = Wbuf + slot * (TPX * KSIZE) + p * KSIZE;
            const int ky0 = part * 2;
#pragma unroll
            for (int r = 0; r < 2; r++) {
                const int ky = ky0 + r;
                if (ky < KH) {               // warp-uniform predicate
                    const float* xr = Xsm + ky * XC + pl;
#pragma unroll
                    for (int kx = 0; kx < KW; kx++)
                        sum = fmaf(wp[ky * KW + kx], xr[kx], sum);
                }
            }
        }
        Red[tid] = sum;
        __syncthreads();                     // compute done; slot reusable

        // Refill this slot with tile t+2 while epilogue runs.
        if (tid == 0 && t + 2 < ntiles) {
            const uint32_t bytes =
                (uint32_t)(min(TPX, npx_blk - (t + 2) * TPX) * KSIZE * 4);
            mbar_expect_tx(mbar0 + 8 * slot, bytes);
            tma_bulk_g2s(wslot_u32 + slot * (TPX * KSIZE * 4),
                         Wg + (size_t)(t + 2) * TPX * KSIZE, bytes,
                         mbar0 + 8 * slot);
        }

        if (tid < TPX) {
            const int po = t * TPX + tid;
            if (po < npx_blk) {
                float s = Red[tid];
#pragma unroll
                for (int k = 1; k < 8; k++) s += Red[k * TPX + tid];
                out[row * OW + px0 + po] = s;
            }
        }
        __syncthreads();                     // Red safe for next tile
    }
}

extern "C" void kernel_launch(void* const* d_in, const int* in_sizes, int n_in,
                              void* d_out, int out_size)
{
    const float* x = (const float*)d_in[0];
    const float* W = (const float*)d_in[1];
    float* out = (float*)d_out;

    cudaFuncSetAttribute(lc2d_kernel,
                         cudaFuncAttributeMaxDynamicSharedMemorySize, SMEM_TOTAL);
    dim3 grid(2, OH);   // half-rows x rows = 872 blocks
    lc2d_kernel<<<grid, THREADS, SMEM_TOTAL>>>(x, W, out);
}

// round 5
// speedup vs baseline: 1.1493x; 1.1493x over previous
#include <cuda_runtime.h>

// Locally-connected 2D: out[oy,ox] = sum_{ky,kx} x[oy+ky, ox+kx] * W[oy,ox,ky,kx]
// x: [450,450] f32, W: [436,436,15,15] f32 (171 MB, streamed once), out: [436,436].
// Warp-per-pixel (best measured shape) + precomputed per-lane x pointers
// (no per-iter ALU) + L2 prefetch of W ~96 pixels ahead to decouple the
// DRAM fetch stream from demand-load miss handling.

#define IN_H 450
#define IN_W 450
#define KH 15
#define KW 15
#define OH 436
#define OW 436
#define KSIZE 225
#define NPIX (OH * OW)     // 190096
#define PFD 96             // prefetch distance in pixels (~86 KB ahead)

__global__ __launch_bounds__(256)
void lc2d_kernel(const float* __restrict__ x,
                 const float* __restrict__ W,
                 float* __restrict__ out)
{
    const int lane = threadIdx.x & 31;
    const int pix  = (blockIdx.x * blockDim.x + threadIdx.x) >> 5;
    if (pix >= NPIX) return;

    const int oy = pix / OW;
    const int ox = pix - oy * OW;

    const float* wp = W + (size_t)pix * KSIZE + lane;

    // L2 prefetch: 8 lanes each pull one 128B line of the W block PFD pixels
    // ahead (8*128B = 1024B covers the 900B block at any alignment).
    if (lane < 8 && pix + PFD < NPIX) {
        const char* pf = (const char*)(W + (size_t)(pix + PFD) * KSIZE) + lane * 128;
        asm volatile("prefetch.global.L2 [%0];" :: "l"(pf));
    }

    // Per-lane x pointers for k = lane + 32*i, i = 0..6 (k <= 223 always).
    const float* xbase = x + oy * IN_W + ox;
    const float* xp0;
    const float* xp1;
    const float* xp2;
    const float* xp3;
    const float* xp4;
    const float* xp5;
    const float* xp6;
    {
        int k, ky;
        k = lane;       ky = k / KW; xp0 = xbase + ky * IN_W + (k - ky * KW);
        k = lane + 32;  ky = k / KW; xp1 = xbase + ky * IN_W + (k - ky * KW);
        k = lane + 64;  ky = k / KW; xp2 = xbase + ky * IN_W + (k - ky * KW);
        k = lane + 96;  ky = k / KW; xp3 = xbase + ky * IN_W + (k - ky * KW);
        k = lane + 128; ky = k / KW; xp4 = xbase + ky * IN_W + (k - ky * KW);
        k = lane + 160; ky = k / KW; xp5 = xbase + ky * IN_W + (k - ky * KW);
        k = lane + 192; ky = k / KW; xp6 = xbase + ky * IN_W + (k - ky * KW);
    }

    // Batch all W loads (independent -> max MLP), then x loads, then FMAs.
    const float w0 = __ldcs(wp);
    const float w1 = __ldcs(wp + 32);
    const float w2 = __ldcs(wp + 64);
    const float w3 = __ldcs(wp + 96);
    const float w4 = __ldcs(wp + 128);
    const float w5 = __ldcs(wp + 160);
    const float w6 = __ldcs(wp + 192);

    const float v0 = __ldg(xp0);
    const float v1 = __ldg(xp1);
    const float v2 = __ldg(xp2);
    const float v3 = __ldg(xp3);
    const float v4 = __ldg(xp4);
    const float v5 = __ldg(xp5);
    const float v6 = __ldg(xp6);

    float s0 = w0 * v0;
    float s1 = w1 * v1;
    s0 = fmaf(w2, v2, s0);
    s1 = fmaf(w3, v3, s1);
    s0 = fmaf(w4, v4, s0);
    s1 = fmaf(w5, v5, s1);
    s0 = fmaf(w6, v6, s0);

    // Tail element k = 224 (ky=14, kx=14): lane 0 only.
    if (lane == 0)
        s1 = fmaf(__ldcs(wp + 224), __ldg(xbase + 14 * IN_W + 14), s1);

    float sum = s0 + s1;
#pragma unroll
    for (int off = 16; off > 0; off >>= 1)
        sum += __shfl_down_sync(0xffffffffu, sum, off);

    if (lane == 0)
        out[pix] = sum;
}

extern "C" void kernel_launch(void* const* d_in, const int* in_sizes, int n_in,
                              void* d_out, int out_size)
{
    const float* x = (const float*)d_in[0];
    const float* W = (const float*)d_in[1];
    float* out = (float*)d_out;

    const int threads = 256;                 // 8 warps = 8 pixels per block
    const int blocks = (NPIX + 7) / 8;       // 23762
    lc2d_kernel<<<blocks, threads>>>(x, W, out);
}

// round 6
// speedup vs baseline: 1.1523x; 1.0026x over previous
#include <cuda_runtime.h>

// Locally-connected 2D: out[oy,ox] = sum_{ky,kx} x[oy+ky, ox+kx] * W[oy,ox,ky,kx]
// x: [450,450] f32, W: [436,436,15,15] f32 (171 MB streamed once), out: [436,436].
// Warp per PIXEL PAIR: the 450-float W block of 2 consecutive pixels is 8B
// aligned -> LDG.64 (halves W load instructions). Lane->x-offset mapping comes
// from a per-block smem table (no divisions in the hot path). Dual
// accumulators route elements to pixel 0/1 at compile time except the one
// straddling unroll step. L2 prefetch keeps the DRAM stream ahead of demand.

#define IN_H 450
#define IN_W 450
#define KH 15
#define KW 15
#define OH 436
#define OW 436
#define KSIZE 225
#define NPIX (OH * OW)       // 190096
#define NPAIR (NPIX / 2)     // 95048
#define PFP 48               // prefetch distance in pairs (96 pixels ahead)

__global__ __launch_bounds__(256)
void lc2d_kernel(const float* __restrict__ x,
                 const float* __restrict__ W,
                 float* __restrict__ out)
{
    // Offset table for both pixels of a pair: f in [0,450),
    // k = f mod 225, pixel = f / 225; xoff2[f] = (k/15)*IN_W + k%15 + pixel.
    __shared__ int xoff2[450];
    {
        const int t = threadIdx.x;
        for (int f = t; f < 450; f += 256) {
            const int pp = (f >= KSIZE) ? 1 : 0;
            const int k  = f - KSIZE * pp;
            const int ky = k / KW;
            xoff2[f] = ky * IN_W + (k - ky * KW) + pp;
        }
    }
    __syncthreads();

    const int lane = threadIdx.x & 31;
    const int pair = (blockIdx.x * blockDim.x + threadIdx.x) >> 5;
    if (pair >= NPAIR) return;

    const int pix0 = pair * 2;
    const int oy = pix0 / OW;
    const int ox = pix0 - oy * OW;                 // pair never crosses a row (OW even)

    const float2* W2 = (const float2*)(W + (size_t)pair * 450) + lane;
    const float*  xb = x + oy * IN_W + ox;
    const int2*   ot = (const int2*)xoff2 + lane;

    // L2 prefetch: 15 lanes cover the 1800B W block PFP pairs ahead.
    if (lane < 15 && pair + PFP < NPAIR) {
        const char* pf = (const char*)(W + (size_t)(pair + PFP) * 450) + lane * 128;
        asm volatile("prefetch.global.L2 [%0];" :: "l"(pf));
    }

    float acc0 = 0.0f, acc1 = 0.0f;

    // i = 0..2 : f = 2*(lane+32i)+{0,1} <= 191  -> all pixel 0
#pragma unroll
    for (int i = 0; i < 3; i++) {
        const float2 w = __ldcs(W2 + 32 * i);
        const int2   o = ot[32 * i];
        acc0 = fmaf(w.x, __ldg(xb + o.x), acc0);
        acc0 = fmaf(w.y, __ldg(xb + o.y), acc0);
    }
    // i = 3 : straddles f = 225 (lane-dependent routing)
    {
        const float2 w = __ldcs(W2 + 96);
        const int2   o = ot[96];
        const float xa = __ldg(xb + o.x);
        const float xbv = __ldg(xb + o.y);
        if (lane <= 16) acc0 = fmaf(w.x, xa, acc0);
        else            acc1 = fmaf(w.x, xa, acc1);
        if (lane <= 15) acc0 = fmaf(w.y, xbv, acc0);
        else            acc1 = fmaf(w.y, xbv, acc1);
    }
    // i = 4..6 : f >= 256 -> all pixel 1
#pragma unroll
    for (int i = 4; i < 7; i++) {
        const float2 w = __ldcs(W2 + 32 * i);
        const int2   o = ot[32 * i];
        acc1 = fmaf(w.x, __ldg(xb + o.x), acc1);
        acc1 = fmaf(w.y, __ldg(xb + o.y), acc1);
    }
    // tail: m = 224 (f = 448,449 -> pixel 1, k = 223,224), lane 0 only
    if (lane == 0) {
        const float2 w = __ldcs(W2 + 224);          // W2 already +lane (=0)
        const int2   o = ((const int2*)xoff2)[224];
        acc1 = fmaf(w.x, __ldg(xb + o.x), acc1);
        acc1 = fmaf(w.y, __ldg(xb + o.y), acc1);
    }

    // Two interleaved warp reductions (independent chains -> ILP)
#pragma unroll
    for (int off = 16; off > 0; off >>= 1) {
        acc0 += __shfl_down_sync(0xffffffffu, acc0, off);
        acc1 += __shfl_down_sync(0xffffffffu, acc1, off);
    }

    if (lane == 0) {
        out[pix0]     = acc0;
        out[pix0 + 1] = acc1;
    }
}

extern "C" void kernel_launch(void* const* d_in, const int* in_sizes, int n_in,
                              void* d_out, int out_size)
{
    const float* x = (const float*)d_in[0];
    const float* W = (const float*)d_in[1];
    float* out = (float*)d_out;

    const int threads = 256;                    // 8 warps = 8 pairs = 16 px/block
    const int blocks = (NPAIR + 7) / 8;         // 11881 (exact)
    lc2d_kernel<<<blocks, threads>>>(x, W, out);
}